// round 8
// baseline (speedup 1.0000x reference)
#include <cuda_runtime.h>

// AllZeroDigitalFilter: time-varying FIR, 50 taps, frame period 80.
// y[b,t] = sum_{j=0..49} x[b, t+j-49] * h[b,t,j]
// h[t=n*80+p][j] = (1-p/80)*bf[n][j] + (p/80)*bf[min(n+1,N-1)][j], bf[n][j]=b[n][49-j]
// Split: y = a0 + w*a1, a0 = sum x*cL, a1 = sum x*(cR-cL).
// (a0,a1) packed in a 64-bit pair, advanced with fma.rn.f32x2 (FFMA2).
// Coefficients interleaved (cL,cD) -> one LDS.64 broadcast per tap.
// x duplicated (v,v) -> one LDS.64 per tap, odd float2 stride = conflict-free.
// Window kept in a CIRCULAR register file (compile-time indices, no shift MOVs).

#define TAPS     50
#define FP       80
#define FPB      10            // frames per block
#define THREADS  160           // 16 threads/frame, exactly 5 warps
#define KOUT     5             // outputs per thread (16*5 = 80 = FP)
#define XWIN     (FPB * FP + TAPS)   // 850 samples: [t0-49, t0+801)

typedef unsigned long long u64;

__device__ __forceinline__ void unpack2(u64 v, float& a, float& b) {
    asm("mov.b64 {%0, %1}, %2;" : "=f"(a), "=f"(b) : "l"(v));
}
__device__ __forceinline__ u64 ffma2(u64 a, u64 b, u64 c) {
    u64 d;
    asm("fma.rn.f32x2 %0, %1, %2, %3;" : "=l"(d) : "l"(a), "l"(b), "l"(c));
    return d;
}

__global__ __launch_bounds__(THREADS, 10)
void azdf_kernel(const float* __restrict__ x,
                 const float* __restrict__ b,
                 float* __restrict__ y,
                 int T, int Nf)
{
    __shared__ float2 sx2[XWIN];          // (v, v) duplicated samples, 6.8 KB
    __shared__ float2 sC[FPB * TAPS];     // (cL, cR-cL) interleaved, 4 KB

    const int bb = blockIdx.y;
    const int n0 = blockIdx.x * FPB;
    const int t0 = n0 * FP;

    const float* xb  = x + (long long)bb * T;
    const float* bbp = b + (long long)bb * Nf * TAPS;

    // ---- stage x window, duplicated ----
    for (int i = threadIdx.x; i < XWIN; i += THREADS) {
        int g = t0 - (TAPS - 1) + i;
        float v = (g >= 0 && g < T) ? xb[g] : 0.0f;
        sx2[i] = make_float2(v, v);
    }

    // ---- stage coefficients: flip + diff, interleaved ----
    for (int idx = threadIdx.x; idx < FPB * TAPS; idx += THREADS) {
        int r = idx / TAPS;
        int j = idx - r * TAPS;
        int n  = n0 + r;
        int n1 = min(n + 1, Nf - 1);
        float l  = bbp[n  * TAPS + (TAPS - 1 - j)];
        float rr = bbp[n1 * TAPS + (TAPS - 1 - j)];
        sC[idx] = make_float2(l, rr - l);
    }
    __syncthreads();

    // ---- per-thread: 5 consecutive outputs within one frame ----
    const int f  = threadIdx.x >> 4;      // frame within block (16 threads/frame)
    const int q  = threadIdx.x & 15;      // 5-output group within frame
    const int lt = 5 * threadIdx.x;       // == f*80 + q*5

    const u64* xp = (const u64*)sx2 + lt; // per-thread stride 5 float2 (odd): conflict-free
    const u64* cp = (const u64*)(sC + f * TAPS);

    u64 acc[KOUT];
    u64 xw[KOUT];                         // circular window: xw[i] holds x[lt + m] with m%5==i
    #pragma unroll
    for (int k = 0; k < KOUT; ++k) {
        acc[k] = 0ULL;
        xw[k]  = xp[k];
    }

    #pragma unroll
    for (int j = 0; j < TAPS; ++j) {
        u64 c2 = cp[j];                   // LDS.64 broadcast: packed (cL, cD)
        #pragma unroll
        for (int k = 0; k < KOUT; ++k)
            acc[k] = ffma2(xw[(j + k) % KOUT], c2, acc[k]);   // compile-time index
        xw[j % KOUT] = xp[j + KOUT];      // overwrite consumed slot; no shift MOVs
    }

    // ---- interpolate + store ----
    const float p0 = (float)(q * KOUT);
    float* yp = y + (long long)bb * T + t0 + lt;
    #pragma unroll
    for (int k = 0; k < KOUT; ++k) {
        float a0, a1;
        unpack2(acc[k], a0, a1);
        float w = (p0 + (float)k) * (1.0f / (float)FP);
        yp[k] = fmaf(w, a1, a0);
    }
}

extern "C" void kernel_launch(void* const* d_in, const int* in_sizes, int n_in,
                              void* d_out, int out_size)
{
    const float* x = (const float*)d_in[0];   // (B, T) float32
    const float* b = (const float*)d_in[1];   // (B, N, 50) float32
    float* y = (float*)d_out;                 // (B, T) float32

    const int Nf = 3000;
    const int T  = Nf * FP;                   // 240000
    const int B  = in_sizes[0] / T;           // 8

    dim3 grid(Nf / FPB, B);                   // (300, 8) = 2400 blocks
    azdf_kernel<<<grid, THREADS>>>(x, b, y, T, Nf);
}

// round 11
// speedup vs baseline: 1.4785x; 1.4785x over previous
#include <cuda_runtime.h>

// AllZeroDigitalFilter: time-varying FIR, 50 taps, frame period 80.
// y[b,t] = sum_{j=0..49} x[b, t+j-49] * h[b,t,j]
// h[t=n*80+p][j] = (1-p/80)*bf[n][j] + (p/80)*bf[min(n+1,N-1)][j], bf[n][j]=b[n][49-j]
// Split: y = a0 + w*a1, a0 = sum x*cL, a1 = sum x*(cR-cL).
// (a0,a1) packed in a 64-bit pair, advanced with fma.rn.f32x2 (FFMA2).
// Coefficients interleaved (cL,cD) -> one LDS.64 broadcast per tap.
// x duplicated (v,v) -> one LDS.64 per tap, odd float2 stride = conflict-free.
// Window rotation via NAMED registers in a 5-tap phase-rotated macro group:
// no shift MOVs, no dynamic indexing, independent of unrolling decisions.

#define TAPS     50
#define FP       80
#define FPB      10            // frames per block
#define THREADS  160           // 16 threads/frame, exactly 5 warps
#define KOUT     5             // outputs per thread (16*5 = 80 = FP)
#define XWIN     (FPB * FP + TAPS)   // 850 samples: [t0-49, t0+801)

typedef unsigned long long u64;

__device__ __forceinline__ void unpack2(u64 v, float& a, float& b) {
    asm("mov.b64 {%0, %1}, %2;" : "=f"(a), "=f"(b) : "l"(v));
}
__device__ __forceinline__ u64 ffma2(u64 a, u64 b, u64 c) {
    u64 d;
    asm("fma.rn.f32x2 %0, %1, %2, %3;" : "=l"(d) : "l"(a), "l"(b), "l"(c));
    return d;
}

__global__ __launch_bounds__(THREADS, 10)
void azdf_kernel(const float* __restrict__ x,
                 const float* __restrict__ b,
                 float* __restrict__ y,
                 int T, int Nf)
{
    __shared__ float2 sx2[XWIN];          // (v, v) duplicated samples, 6.8 KB
    __shared__ float2 sC[FPB * TAPS];     // (cL, cR-cL) interleaved, 4 KB

    const int bb = blockIdx.y;
    const int n0 = blockIdx.x * FPB;
    const int t0 = n0 * FP;

    const float* xb  = x + (long long)bb * T;
    const float* bbp = b + (long long)bb * Nf * TAPS;

    // ---- stage x window, duplicated ----
    for (int i = threadIdx.x; i < XWIN; i += THREADS) {
        int g = t0 - (TAPS - 1) + i;
        float v = (g >= 0 && g < T) ? xb[g] : 0.0f;
        sx2[i] = make_float2(v, v);
    }

    // ---- stage coefficients: flip + diff, interleaved ----
    for (int idx = threadIdx.x; idx < FPB * TAPS; idx += THREADS) {
        int r = idx / TAPS;
        int j = idx - r * TAPS;
        int n  = n0 + r;
        int n1 = min(n + 1, Nf - 1);
        float l  = bbp[n  * TAPS + (TAPS - 1 - j)];
        float rr = bbp[n1 * TAPS + (TAPS - 1 - j)];
        sC[idx] = make_float2(l, rr - l);
    }
    __syncthreads();

    // ---- per-thread: 5 consecutive outputs within one frame ----
    const int f  = threadIdx.x >> 4;      // frame within block (16 threads/frame)
    const int q  = threadIdx.x & 15;      // 5-output group within frame
    const int lt = 5 * threadIdx.x;       // == f*80 + q*5

    const u64* xp = (const u64*)sx2 + lt; // per-thread stride 5 float2 (odd): conflict-free
    const u64* cp = (const u64*)(sC + f * TAPS);

    u64 acc0 = 0, acc1 = 0, acc2 = 0, acc3 = 0, acc4 = 0;
    u64 xw0 = xp[0], xw1 = xp[1], xw2 = xp[2], xw3 = xp[3], xw4 = xp[4];

    // At tap j (phase r=j%5): slot r holds x[lt+j]; acc_k uses slot (r+k)%5.
    // After the 5 FFMA2s, slot r is refilled with x[lt+j+5].
#define TAP(r, XA, XB, XC, XD, XE)                         \
    {                                                      \
        u64 c2 = cp[j0 + (r)];                             \
        acc0 = ffma2(XA, c2, acc0);                        \
        acc1 = ffma2(XB, c2, acc1);                        \
        acc2 = ffma2(XC, c2, acc2);                        \
        acc3 = ffma2(XD, c2, acc3);                        \
        acc4 = ffma2(XE, c2, acc4);                        \
        XA = xp[j0 + (r) + KOUT];                          \
    }

    #pragma unroll
    for (int g = 0; g < TAPS / KOUT; ++g) {   // 10 groups of 5 taps
        const int j0 = g * KOUT;
        TAP(0, xw0, xw1, xw2, xw3, xw4)
        TAP(1, xw1, xw2, xw3, xw4, xw0)
        TAP(2, xw2, xw3, xw4, xw0, xw1)
        TAP(3, xw3, xw4, xw0, xw1, xw2)
        TAP(4, xw4, xw0, xw1, xw2, xw3)
    }
#undef TAP

    // ---- interpolate + store ----
    const float p0 = (float)(q * KOUT);
    float* yp = y + (long long)bb * T + t0 + lt;
    float a0, a1;
    unpack2(acc0, a0, a1); yp[0] = fmaf((p0 + 0.0f) * (1.0f / FP), a1, a0);
    unpack2(acc1, a0, a1); yp[1] = fmaf((p0 + 1.0f) * (1.0f / FP), a1, a0);
    unpack2(acc2, a0, a1); yp[2] = fmaf((p0 + 2.0f) * (1.0f / FP), a1, a0);
    unpack2(acc3, a0, a1); yp[3] = fmaf((p0 + 3.0f) * (1.0f / FP), a1, a0);
    unpack2(acc4, a0, a1); yp[4] = fmaf((p0 + 4.0f) * (1.0f / FP), a1, a0);
}

extern "C" void kernel_launch(void* const* d_in, const int* in_sizes, int n_in,
                              void* d_out, int out_size)
{
    const float* x = (const float*)d_in[0];   // (B, T) float32
    const float* b = (const float*)d_in[1];   // (B, N, 50) float32
    float* y = (float*)d_out;                 // (B, T) float32

    const int Nf = 3000;
    const int T  = Nf * FP;                   // 240000
    const int B  = in_sizes[0] / T;           // 8

    dim3 grid(Nf / FPB, B);                   // (300, 8) = 2400 blocks
    azdf_kernel<<<grid, THREADS>>>(x, b, y, T, Nf);
}

// round 12
// speedup vs baseline: 1.7617x; 1.1915x over previous
#include <cuda_runtime.h>

// AllZeroDigitalFilter: time-varying FIR, 50 taps, frame period 80.
// y[b,t] = sum_{j=0..49} x[b, t+j-49] * h[b,t,j]
// h[t=n*80+p][j] = (1-p/80)*bf[n][j] + (p/80)*bf[min(n+1,N-1)][j], bf[n][j]=b[n][49-j]
// Split: y = a0 + w*a1, a0 = sum x*cL, a1 = sum x*(cR-cL).
// (a0,a1) packed in a 64-bit pair, advanced with fma.rn.f32x2 (FFMA2).
// Taps processed in PAIRS: one LDS.128 = 2 taps' (cL,cD); one LDS.64 = 2 x samples
// (x stored un-duplicated; pack2 MOVs rebuild (v,v)). 6-slot named-register
// circular window, compile-time indices. KOUT=4 -> 16B-aligned bases for
// LDS.128 and STG.128.

#define TAPS     50
#define FP       80
#define FPB      8             // frames per block
#define THREADS  160           // 20 threads/frame, exactly 5 warps
#define KOUT     4             // outputs per thread (20*4 = 80 = FP)
#define XWIN     (FPB * FP + 56)   // 696: [t0-49, ...), padded for last refill

typedef unsigned long long u64;

__device__ __forceinline__ u64 pack2(float v) {       // (v, v)
    u64 r;
    asm("mov.b64 %0, {%1, %1};" : "=l"(r) : "f"(v));
    return r;
}
__device__ __forceinline__ void unpack2(u64 v, float& a, float& b) {
    asm("mov.b64 {%0, %1}, %2;" : "=f"(a), "=f"(b) : "l"(v));
}
__device__ __forceinline__ u64 ffma2(u64 a, u64 b, u64 c) {
    u64 d;
    asm("fma.rn.f32x2 %0, %1, %2, %3;" : "=l"(d) : "l"(a), "l"(b), "l"(c));
    return d;
}

__global__ __launch_bounds__(THREADS, 12)
void azdf_kernel(const float* __restrict__ x,
                 const float* __restrict__ b,
                 float* __restrict__ y,
                 int T, int Nf)
{
    __shared__ float  sxf[XWIN];           // plain x window, 2.8 KB
    __shared__ float2 sC[FPB * TAPS];      // (cL, cR-cL) interleaved, 3.2 KB

    const int bb = blockIdx.y;
    const int n0 = blockIdx.x * FPB;
    const int t0 = n0 * FP;

    const float* xb  = x + (long long)bb * T;
    const float* bbp = b + (long long)bb * Nf * TAPS;

    // ---- stage x window ----
    for (int i = threadIdx.x; i < XWIN; i += THREADS) {
        int g = t0 - (TAPS - 1) + i;
        sxf[i] = (g >= 0 && g < T) ? xb[g] : 0.0f;
    }

    // ---- stage coefficients: flip + diff, interleaved ----
    for (int idx = threadIdx.x; idx < FPB * TAPS; idx += THREADS) {
        int r = idx / TAPS;
        int j = idx - r * TAPS;
        int n  = n0 + r;
        int n1 = min(n + 1, Nf - 1);
        float l  = bbp[n  * TAPS + (TAPS - 1 - j)];
        float rr = bbp[n1 * TAPS + (TAPS - 1 - j)];
        sC[idx] = make_float2(l, rr - l);
    }
    __syncthreads();

    // ---- per-thread: 4 consecutive outputs within one frame ----
    const int f  = threadIdx.x / 20;       // frame within block (20 threads/frame)
    const int q  = threadIdx.x - f * 20;   // 4-output group within frame
    const int lt = 4 * threadIdx.x;        // == f*80 + q*4 (16B-aligned base)

    const float2*     xf2   = (const float2*)(sxf + lt);       // 8B-aligned pairs
    const ulonglong2* cp128 = (const ulonglong2*)(sC + f * TAPS); // 16B-aligned

    u64 acc0 = 0, acc1 = 0, acc2 = 0, acc3 = 0;

    // 6-slot circular window: slot s holds x[lt + m] with m % 6 == s (duplicated).
    u64 xw0, xw1, xw2, xw3, xw4, xw5;
    {
        float2 p0 = xf2[0], p1 = xf2[1], p2 = xf2[2];
        xw0 = pack2(p0.x); xw1 = pack2(p0.y);
        xw2 = pack2(p1.x); xw3 = pack2(p1.y);
        xw4 = pack2(p2.x); xw5 = pack2(p2.y);
    }

    // Tap pair (j, j+1), j even, phase r = j % 6 handled by name permutation:
    // X0..X5 name slots r..r+5 (mod 6). Tap j uses X0..X3, tap j+1 uses X1..X4.
    // Then samples j, j+1 (slots X0, X1) are refilled with j+6, j+7.
#define TAPPAIR(J, X0, X1, X2, X3, X4, X5)             \
    {                                                  \
        ulonglong2 cc = cp128[(J) >> 1];               \
        acc0 = ffma2(X0, cc.x, acc0);                  \
        acc1 = ffma2(X1, cc.x, acc1);                  \
        acc2 = ffma2(X2, cc.x, acc2);                  \
        acc3 = ffma2(X3, cc.x, acc3);                  \
        acc0 = ffma2(X1, cc.y, acc0);                  \
        acc1 = ffma2(X2, cc.y, acc1);                  \
        acc2 = ffma2(X3, cc.y, acc2);                  \
        acc3 = ffma2(X4, cc.y, acc3);                  \
        float2 xx = xf2[((J) + 6) >> 1];               \
        X0 = pack2(xx.x);                              \
        X1 = pack2(xx.y);                              \
    }

    #pragma unroll
    for (int gg = 0; gg < 8; ++gg) {       // taps 0..47 in 8 triples of pair-groups
        const int j0 = 6 * gg;
        TAPPAIR(j0 + 0, xw0, xw1, xw2, xw3, xw4, xw5)
        TAPPAIR(j0 + 2, xw2, xw3, xw4, xw5, xw0, xw1)
        TAPPAIR(j0 + 4, xw4, xw5, xw0, xw1, xw2, xw3)
    }
    TAPPAIR(48, xw0, xw1, xw2, xw3, xw4, xw5)   // taps 48,49 (refill reads padded smem)
#undef TAPPAIR

    // ---- interpolate + vector store ----
    const float p0f = (float)(q * KOUT);
    float a0, a1;
    float4 out;
    unpack2(acc0, a0, a1); out.x = fmaf((p0f + 0.0f) * (1.0f / FP), a1, a0);
    unpack2(acc1, a0, a1); out.y = fmaf((p0f + 1.0f) * (1.0f / FP), a1, a0);
    unpack2(acc2, a0, a1); out.z = fmaf((p0f + 2.0f) * (1.0f / FP), a1, a0);
    unpack2(acc3, a0, a1); out.w = fmaf((p0f + 3.0f) * (1.0f / FP), a1, a0);
    *(float4*)(y + (long long)bb * T + t0 + lt) = out;   // 16B-aligned STG.128
}

extern "C" void kernel_launch(void* const* d_in, const int* in_sizes, int n_in,
                              void* d_out, int out_size)
{
    const float* x = (const float*)d_in[0];   // (B, T) float32
    const float* b = (const float*)d_in[1];   // (B, N, 50) float32
    float* y = (float*)d_out;                 // (B, T) float32

    const int Nf = 3000;
    const int T  = Nf * FP;                   // 240000
    const int B  = in_sizes[0] / T;           // 8

    dim3 grid(Nf / FPB, B);                   // (375, 8) = 3000 blocks
    azdf_kernel<<<grid, THREADS>>>(x, b, y, T, Nf);
}